// round 15
// baseline (speedup 1.0000x reference)
#include <cuda_runtime.h>
#include <cuda_bf16.h>
#include <string.h>

// Problem constants (static shapes from the reference)
#define NPTS   32768          // 8 * 4096 points (contiguous in output)
#define NROWS  4096           // 64 * 64 (m,n) pairs
#define NBASIS 23

// Scratch: poly[k][p], k-major so GEMM-side loads are coalesced.
__device__ float g_poly[NBASIS * NPTS];

// ---------------------------------------------------------------------------
// Kernel 1: per-point hydrogen wavefunction basis (validated rel_err 1.2e-7).
// ---------------------------------------------------------------------------
__global__ void basis_kernel(const float* __restrict__ pos) {
    int p = blockIdx.x * blockDim.x + threadIdx.x;
    if (p >= NPTS) return;

    float x = pos[3 * p + 0], y = pos[3 * p + 1], z = pos[3 * p + 2];
    float r    = sqrtf(x * x + y * y + z * z) + 1e-12f;
    float invr = 1.0f / r;
    float xs = x * invr, ys = y * invr, ct = z * invr;

    float e1 = expf(-r), e2 = expf(-0.5f * r);
    float e3 = expf(-r * (1.0f / 3.0f)), e4 = expf(-0.25f * r);

    const float C00 = 0.28209479177387814f;
    const float K10 = 0.4886025119029199f;
    const float C21 = 1.0925484305920792f;
    const float C22 = 0.5462742152960396f;
    const float C20 = 0.31539156525252005f;

    float Y1m1 = -K10 * ys, Y10 = K10 * ct, Y1p1 = -K10 * xs;
    float Y2m2 =  C21 * xs * ys;
    float Y2m1 = -C21 * ys * ct;
    float Y20  =  C20 * (3.0f * ct * ct - 1.0f);
    float Y2p1 = -C21 * xs * ct;
    float Y2p2 =  C22 * (xs * xs - ys * ys);

    float R10 = 2.0f * e1;
    float R20 = 0.35355339059327373f * e2 * (2.0f - r);
    float R21 = 0.2041241452319315f  * e2 * r;

    float rho3 = (2.0f / 3.0f) * r;
    float R30 = 0.1283000598199168f   * e3 * (3.0f - 3.0f * rho3 + 0.5f * rho3 * rho3);
    float R31 = 0.045360921162019494f * e3 * rho3 * (4.0f - rho3);
    float R32 = 0.02028602242947916f  * e3 * rho3 * rho3;

    float rho4 = 0.5f * r;
    float R40 = 0.0625f * e4 *
                (4.0f - 6.0f * rho4 + 2.0f * rho4 * rho4 - rho4 * rho4 * rho4 * (1.0f / 6.0f));
    float R41 = 0.016137430609197573f * e4 * rho4 * (10.0f - 5.0f * rho4 + 0.5f * rho4 * rho4);
    float R42 = 0.004658474194686761f * e4 * rho4 * rho4 * (6.0f - rho4);

    float v[NBASIS];
    v[0]  = R10 * C00;
    v[1]  = R20 * C00;
    v[2]  = R21 * Y1m1;  v[3]  = R21 * Y10;  v[4]  = R21 * Y1p1;
    v[5]  = R30 * C00;
    v[6]  = R31 * Y1m1;  v[7]  = R31 * Y10;  v[8]  = R31 * Y1p1;
    v[9]  = R32 * Y2m2;  v[10] = R32 * Y2m1; v[11] = R32 * Y20;
    v[12] = R32 * Y2p1;  v[13] = R32 * Y2p2;
    v[14] = R40 * C00;
    v[15] = R41 * Y1m1;  v[16] = R41 * Y10;  v[17] = R41 * Y1p1;
    v[18] = R42 * Y2m2;  v[19] = R42 * Y2m1; v[20] = R42 * Y20;
    v[21] = R42 * Y2p1;  v[22] = R42 * Y2p2;

#pragma unroll
    for (int k = 0; k < NBASIS; k++) g_poly[k * NPTS + p] = v[k];
}

// ---------------------------------------------------------------------------
// Kernel 2: out(4096 x 32768) = coeff(4096 x 23) @ poly(23 x 32768)
// f32x2 GEMM, W=4 points/thread, RI=8 rows/iter (dup-sharing):
//   - the {p,p} dups depend only on k, so BOTH 4-row groups in one k-step
//     share them: per k = 2 LDS.128 + 4 dups + 16 fma2
//   - coeff pairs {c_r,c_{r+1}} read directly as ulonglong2 from k-major smem
//   - TPB=128, launch_bounds(128,2): 8 warps/SM but ~160-reg budget with NO
//     spill -> ptxas hoists LDS aggressively (latency hiding via ILP, not
//     occupancy)
//   - 4 adjacent points -> one STG.128 per row, streaming
// ---------------------------------------------------------------------------
#define TPB   128
#define PT    512    // points per block (4 adjacent per thread)
#define RT    128    // coefficient rows per block
#define RI    8      // rows per inner iteration (2 groups share dups)

typedef unsigned long long ull;

__device__ __forceinline__ ull dup2(float v) {
    ull u;
    asm("mov.b64 %0, {%1, %1};" : "=l"(u) : "f"(v));
    return u;
}
__device__ __forceinline__ void fma2(ull& acc, ull a, ull b) {
    asm("fma.rn.f32x2 %0, %1, %2, %0;" : "+l"(acc) : "l"(a), "l"(b));
}
__device__ __forceinline__ void unpk(ull u, float& lo, float& hi) {
    asm("mov.b64 {%0, %1}, %2;" : "=f"(lo), "=f"(hi) : "l"(u));
}

__global__ __launch_bounds__(TPB, 2) void gemm_kernel(const float* __restrict__ coeff,
                                                      float* __restrict__ out) {
    __shared__ __align__(16) float cs[NBASIS * RT];   // k-major: cs[k*RT + row]

    int tid = threadIdx.x;
    int p0  = blockIdx.x * PT + 4 * tid;  // four adjacent points p0..p0+3
    int r0  = blockIdx.y * RT;

    // Stage coefficient tile transposed to k-major.
    for (int i = tid; i < NBASIS * RT; i += TPB) {
        int k  = i / RT;
        int rr = i - k * RT;
        cs[i] = coeff[(r0 + rr) * NBASIS + k];
    }

    // Poly for this thread's 4 points: 23 x float4 = 92 scalar regs.
    float4 pv[NBASIS];
#pragma unroll
    for (int k = 0; k < NBASIS; k++)
        pv[k] = *reinterpret_cast<const float4*>(&g_poly[k * NPTS + p0]);
    __syncthreads();

    for (int rj = 0; rj < RT; rj += RI) {
        // a[g][i]: rows {rj+2g, rj+2g+1} for point p0+i   (16 ull = 32 regs)
        ull a[4][4];
#pragma unroll
        for (int g = 0; g < 4; g++)
#pragma unroll
            for (int i = 0; i < 4; i++) a[g][i] = 0ull;

#pragma unroll
        for (int k = 0; k < NBASIS; k++) {
            const float* ck = &cs[k * RT + rj];
            ulonglong2 cp0 = *reinterpret_cast<const ulonglong2*>(ck);      // rows rj..rj+3
            ulonglong2 cp1 = *reinterpret_cast<const ulonglong2*>(ck + 4);  // rows rj+4..rj+7
            ull d0 = dup2(pv[k].x);   // 4 dups per k, shared by 16 fma2
            ull d1 = dup2(pv[k].y);
            ull d2 = dup2(pv[k].z);
            ull d3 = dup2(pv[k].w);
            fma2(a[0][0], cp0.x, d0);  fma2(a[0][1], cp0.x, d1);
            fma2(a[0][2], cp0.x, d2);  fma2(a[0][3], cp0.x, d3);
            fma2(a[1][0], cp0.y, d0);  fma2(a[1][1], cp0.y, d1);
            fma2(a[1][2], cp0.y, d2);  fma2(a[1][3], cp0.y, d3);
            fma2(a[2][0], cp1.x, d0);  fma2(a[2][1], cp1.x, d1);
            fma2(a[2][2], cp1.x, d2);  fma2(a[2][3], cp1.x, d3);
            fma2(a[3][0], cp1.y, d0);  fma2(a[3][1], cp1.y, d1);
            fma2(a[3][2], cp1.y, d2);  fma2(a[3][3], cp1.y, d3);
        }

        // Stores: row rj+2g = lo halves of a[g][0..3], row rj+2g+1 = hi halves.
        float* ob = out + (size_t)(r0 + rj) * NPTS + p0;
#pragma unroll
        for (int g = 0; g < 4; g++) {
            float l0, h0, l1, h1, l2, h2, l3, h3;
            unpk(a[g][0], l0, h0);
            unpk(a[g][1], l1, h1);
            unpk(a[g][2], l2, h2);
            unpk(a[g][3], l3, h3);
            __stcs(reinterpret_cast<float4*>(ob + (size_t)(2 * g) * NPTS),
                   make_float4(l0, l1, l2, l3));
            __stcs(reinterpret_cast<float4*>(ob + (size_t)(2 * g + 1) * NPTS),
                   make_float4(h0, h1, h2, h3));
        }
    }
}

// ---------------------------------------------------------------------------
// Launch: [0] position (8*4096*3 f32), [1] coefficients (64*64*23 f32).
// Output: (64,64,8,4096) f32 = out[row][point].
// ---------------------------------------------------------------------------
extern "C" void kernel_launch(void* const* d_in, const int* in_sizes, int n_in,
                              void* d_out, int out_size) {
    const float* pos   = (const float*)d_in[0];
    const float* coeff = (const float*)d_in[1];
    float* out = (float*)d_out;

    basis_kernel<<<NPTS / 256, 256>>>(pos);

    dim3 grid(NPTS / PT, NROWS / RT);   // (64, 32)
    gemm_kernel<<<grid, TPB>>>(coeff, out);
}